// round 11
// baseline (speedup 1.0000x reference)
#include <cuda_runtime.h>
#include <cstdint>

#define NNODES 64
#define NEDGES 128
#define NGRAPH 4

typedef unsigned long long ull;

#define O1 2000
#define O2 500
#define O3 100
#define K1 9
#define K2 2000
#define K3 500

// ---------------- scratch ----------------
__device__ float g_P  [5 * 64 * 64];      // P_j[n][m]: j*4096 + n*64 + m
__device__ float g_A1T[6 * K1 * 64];      // 54 x 64
__device__ float g_A2T[6 * K2 * 64];      // 12000 x 64
__device__ float g_A3T[6 * K3 * 64];      // 3000 x 64
__device__ float g_Z1 [64 * O1];
__device__ float g_Z2 [64 * O2];
__device__ float g_Z3 [64 * O3];

// ---------------- helpers ----------------
__device__ __forceinline__ void gdc_wait() {
    asm volatile("griddepcontrol.wait;" ::: "memory");
}
__device__ __forceinline__ void gdc_launch() {
    asm volatile("griddepcontrol.launch_dependents;" ::: "memory");
}
__device__ __forceinline__ ull dup2(float x) {
    ull r; asm("mov.b64 %0, {%1, %1};" : "=l"(r) : "f"(x)); return r;
}
__device__ __forceinline__ void fma2(ull &d, ull a, ull b) {
    asm("fma.rn.f32x2 %0, %1, %2, %3;" : "=l"(d) : "l"(a), "l"(b), "l"(d));
}
__device__ __forceinline__ float2 unpk(ull v) {
    float2 r; asm("mov.b64 {%0, %1}, %2;" : "=f"(r.x), "=f"(r.y) : "l"(v)); return r;
}
__device__ __forceinline__ void cpa16(void* dst, const void* src) {
    uint32_t d = (uint32_t)__cvta_generic_to_shared(dst);
    asm volatile("cp.async.cg.shared.global [%0], [%1], 16;\n" :: "r"(d), "l"(src));
}
__device__ __forceinline__ void cpa_commit() {
    asm volatile("cp.async.commit_group;\n" ::: "memory");
}
template<int N> __device__ __forceinline__ void cpa_wait() {
    asm volatile("cp.async.wait_group %0;\n" :: "n"(N) : "memory");
}

// ================= prep: build P, layer-1 A'' (edge scatter), zero Z2/Z3 =================
__global__ __launch_bounds__(128) void prep(
    const float* __restrict__ x, const int* __restrict__ eidx,
    const float* __restrict__ eattr)
{
    gdc_wait();
    gdc_launch();
    const int t = threadIdx.x;

    if (blockIdx.x == 1) {   // zero atomic accumulators Z2, Z3
        float4* z2 = (float4*)g_Z2;
        for (int i = t; i < (64 * O2) / 4; i += 128) z2[i] = make_float4(0,0,0,0);
        float4* z3 = (float4*)g_Z3;
        for (int i = t; i < (64 * O3) / 4; i += 128) z3[i] = make_float4(0,0,0,0);
        return;
    }
    // block 0: zero P and M-part of A1T
    for (int i = t; i < 5 * 64 * 64; i += 128) g_P[i] = 0.f;
    for (int i = t; i < 45 * 64;     i += 128) g_A1T[i] = 0.f;
    __syncthreads();

    if (t < NEDGES) {
        int s = eidx[t], d = eidx[NEDGES + t];
        float xs[9];
        #pragma unroll
        for (int i = 0; i < 9; i++) xs[i] = x[s * 9 + i];
        #pragma unroll
        for (int j = 0; j < 4; j++) {
            float w = eattr[t * 4 + j];
            atomicAdd(&g_P[j * 4096 + s * 64 + d], w);
            #pragma unroll
            for (int i = 0; i < 9; i++)
                atomicAdd(&g_A1T[(j * 9 + i) * 64 + d], w * xs[i]);
        }
        atomicAdd(&g_P[4 * 4096 + s * 64 + d], 1.f);
        #pragma unroll
        for (int i = 0; i < 9; i++)
            atomicAdd(&g_A1T[(36 + i) * 64 + d], xs[i]);
    }
    if (t < 64) {   // identity block: A1T rows 45..53 = xT
        #pragma unroll
        for (int i = 0; i < 9; i++)
            g_A1T[(45 + i) * 64 + t] = x[t * 9 + i];
    }
}

// ================= main GEMM: Z[m,o] (+)= sum_r A''T[r][m] * B'[r,o] =================
// B' row r: r<4K -> We + r*O ; r<5K -> be + (r-4K)*O ; else root + (r-5K)*O
// BM=64, BN=128, BK=16, 128 threads, 8x8 f32x2, 3-stage cp.async.
__global__ __launch_bounds__(128) void gemm_main(
    const float* __restrict__ AT, int Kj, int O,
    const float* __restrict__ We, const float* __restrict__ be,
    const float* __restrict__ root, float* __restrict__ Z, int kChunk, int direct)
{
    __shared__ float As[3][16][68];
    __shared__ float Bs[3][16][128];

    gdc_wait();
    gdc_launch();

    const int t    = threadIdx.x;
    const int Ktot = 6 * Kj;
    const int c0   = blockIdx.x * 128;
    const int k0   = blockIdx.y * kChunk;
    const int kend = min(k0 + kChunk, Ktot);
    const int nsteps = (kend - k0 + 15) >> 4;

    const int kkB   = t >> 3;
    const int cbase = (t & 7) * 16;
    const float4 z4 = make_float4(0.f, 0.f, 0.f, 0.f);

    auto stage = [&](int s, int buf) {
        const int kt = k0 + s * 16;
        const int kb = kend - kt;
        #pragma unroll
        for (int i = 0; i < 4; i++) {
            int cl = cbase + 4 * i;
            int c  = c0 + cl;
            float4* bd = (float4*)&Bs[buf][kkB][cl];
            if (kkB < kb && c < O) {
                int rr = kt + kkB;
                const float* P;
                if      (rr < 4 * Kj) P = We   + (size_t)rr * O;
                else if (rr < 5 * Kj) P = be   + (size_t)(rr - 4 * Kj) * O;
                else                  P = root + (size_t)(rr - 5 * Kj) * O;
                cpa16(bd, P + c);
            } else *bd = z4;
        }
        #pragma unroll
        for (int i = 0; i < 2; i++) {
            int q  = t + 128 * i;
            int kk = q >> 4, m4 = (q & 15) * 4;
            float4* ad = (float4*)&As[buf][kk][m4];
            if (kk < kb) cpa16(ad, AT + (size_t)(kt + kk) * 64 + m4);
            else         *ad = z4;
        }
        cpa_commit();
    };

    stage(0, 0);
    if (nsteps > 1) stage(1, 1);

    const int tx = t & 15;
    const int ty = t >> 4;
    ull acc[4][8];
    #pragma unroll
    for (int r = 0; r < 4; r++)
        #pragma unroll
        for (int j = 0; j < 8; j++) acc[r][j] = 0ull;

    for (int s = 0; s < nsteps; s++) {
        const int buf = s % 3;
        if (s + 2 < nsteps)      { stage(s + 2, (s + 2) % 3); cpa_wait<2>(); }
        else if (s + 1 < nsteps) { cpa_wait<1>(); }
        else                     { cpa_wait<0>(); }
        __syncthreads();

        #pragma unroll
        for (int kk = 0; kk < 16; kk++) {
            const float* as = &As[buf][kk][8 * ty];
            ull a0 = *(const ull*)(as);
            ull a1 = *(const ull*)(as + 2);
            ull a2 = *(const ull*)(as + 4);
            ull a3 = *(const ull*)(as + 6);
            float4 bL = *(const float4*)&Bs[buf][kk][4 * tx];
            float4 bH = *(const float4*)&Bs[buf][kk][64 + 4 * tx];
            ull b0 = dup2(bL.x), b1 = dup2(bL.y), b2 = dup2(bL.z), b3 = dup2(bL.w);
            ull b4 = dup2(bH.x), b5 = dup2(bH.y), b6 = dup2(bH.z), b7 = dup2(bH.w);
            fma2(acc[0][0], a0, b0); fma2(acc[0][1], a0, b1); fma2(acc[0][2], a0, b2); fma2(acc[0][3], a0, b3);
            fma2(acc[0][4], a0, b4); fma2(acc[0][5], a0, b5); fma2(acc[0][6], a0, b6); fma2(acc[0][7], a0, b7);
            fma2(acc[1][0], a1, b0); fma2(acc[1][1], a1, b1); fma2(acc[1][2], a1, b2); fma2(acc[1][3], a1, b3);
            fma2(acc[1][4], a1, b4); fma2(acc[1][5], a1, b5); fma2(acc[1][6], a1, b6); fma2(acc[1][7], a1, b7);
            fma2(acc[2][0], a2, b0); fma2(acc[2][1], a2, b1); fma2(acc[2][2], a2, b2); fma2(acc[2][3], a2, b3);
            fma2(acc[2][4], a2, b4); fma2(acc[2][5], a2, b5); fma2(acc[2][6], a2, b6); fma2(acc[2][7], a2, b7);
            fma2(acc[3][0], a3, b0); fma2(acc[3][1], a3, b1); fma2(acc[3][2], a3, b2); fma2(acc[3][3], a3, b3);
            fma2(acc[3][4], a3, b4); fma2(acc[3][5], a3, b5); fma2(acc[3][6], a3, b6); fma2(acc[3][7], a3, b7);
        }
        __syncthreads();
    }

    const int cL = c0 + 4 * tx;
    const int cH = c0 + 64 + 4 * tx;
    #pragma unroll
    for (int rp = 0; rp < 4; rp++) {
        int m = 8 * ty + 2 * rp;
        float2 v[8];
        #pragma unroll
        for (int j = 0; j < 8; j++) v[j] = unpk(acc[rp][j]);
        if (cL < O) {
            if (direct) {
                *(float4*)&Z[(size_t)m       * O + cL] = make_float4(v[0].x, v[1].x, v[2].x, v[3].x);
                *(float4*)&Z[(size_t)(m + 1) * O + cL] = make_float4(v[0].y, v[1].y, v[2].y, v[3].y);
            } else {
                #pragma unroll
                for (int j = 0; j < 4; j++) {
                    atomicAdd(&Z[(size_t)m       * O + cL + j], v[j].x);
                    atomicAdd(&Z[(size_t)(m + 1) * O + cL + j], v[j].y);
                }
            }
        }
        if (cH < O) {
            if (direct) {
                *(float4*)&Z[(size_t)m       * O + cH] = make_float4(v[4].x, v[5].x, v[6].x, v[7].x);
                *(float4*)&Z[(size_t)(m + 1) * O + cH] = make_float4(v[4].y, v[5].y, v[6].y, v[7].y);
            } else {
                #pragma unroll
                for (int j = 0; j < 4; j++) {
                    atomicAdd(&Z[(size_t)m       * O + cH + j], v[4 + j].x);
                    atomicAdd(&Z[(size_t)(m + 1) * O + cH + j], v[4 + j].y);
                }
            }
        }
    }
}

// ================= relu + build next-layer A'' (M_j = P_j^T h, hT) =================
// Block = 16-column tile of h. Outputs rows j*K+k (j<5) and 5K+k of AoutT.
__global__ __launch_bounds__(128) void relu_buildM(
    const float* __restrict__ Z, const float* __restrict__ bias, int K,
    float* __restrict__ AoutT)
{
    __shared__ float sh_h[16][72];
    __shared__ float sh_P[64 * 64];

    gdc_wait();
    gdc_launch();

    const int t  = threadIdx.x;
    const int k0 = blockIdx.x * 16;

    // load + bias + relu + transpose
    for (int i = t; i < 1024; i += 128) {
        int n = i >> 4, kk = i & 15, k = k0 + kk;
        float v = 0.f;
        if (k < K) v = fmaxf(Z[(size_t)n * K + k] + bias[k], 0.f);
        sh_h[kk][n] = v;
    }
    __syncthreads();

    // identity block: AoutT[5K + k][n] = h[n][k]
    for (int i = t; i < 1024; i += 128) {
        int kk = i >> 6, n = i & 63, k = k0 + kk;
        if (k < K) AoutT[(size_t)(5 * K + k) * 64 + n] = sh_h[kk][n];
    }

    const int kk = t >> 3;
    const int m0 = (t & 7) * 8;
    const int k  = k0 + kk;

    for (int j = 0; j < 5; j++) {
        __syncthreads();
        for (int i = t; i < 1024; i += 128)
            ((float4*)sh_P)[i] = ((const float4*)(g_P + j * 4096))[i];
        __syncthreads();

        ull a0c = 0, a1c = 0, a2c = 0, a3c = 0;
        #pragma unroll 8
        for (int n = 0; n < 64; n++) {
            ull a = dup2(sh_h[kk][n]);
            const ull* pr = (const ull*)&sh_P[n * 64 + m0];
            fma2(a0c, a, pr[0]); fma2(a1c, a, pr[1]);
            fma2(a2c, a, pr[2]); fma2(a3c, a, pr[3]);
        }
        if (k < K) {
            float2 v0 = unpk(a0c), v1 = unpk(a1c), v2 = unpk(a2c), v3 = unpk(a3c);
            float* dst = AoutT + (size_t)(j * K + k) * 64 + m0;
            *(float4*)dst       = make_float4(v0.x, v0.y, v1.x, v1.y);
            *(float4*)(dst + 4) = make_float4(v2.x, v2.y, v3.x, v3.y);
        }
    }
}

// ================= fused FCN head (relu of Z3 inlined) =================
__global__ __launch_bounds__(256) void head_fused(
    const float* __restrict__ Z3, const int* __restrict__ batch,
    const float* __restrict__ b3,
    const float* __restrict__ W1, const float* __restrict__ c1,
    const float* __restrict__ W2, const float* __restrict__ c2,
    const float* __restrict__ W3, const float* __restrict__ c3,
    const float* __restrict__ W4, const float* __restrict__ c4,
    float* __restrict__ out)
{
    __shared__ float gS[100];
    __shared__ float s1[1000];
    __shared__ float part[200];
    __shared__ float s2[100];
    __shared__ float s3[50];
    __shared__ int   sb[NNODES];

    gdc_wait();

    const int g = blockIdx.x;
    const int t = threadIdx.x;

    if (t < NNODES) sb[t] = batch[t];
    __syncthreads();

    if (t < 100) {
        float bo = b3[t];
        float a = 0.f;
        for (int n = 0; n < NNODES; n++)
            if (sb[n] == g) a += fmaxf(Z3[n * 100 + t] + bo, 0.f);
        gS[t] = a;
    }
    __syncthreads();

    for (int f = t; f < 1000; f += 256) {
        float a = c1[f];
        for (int kq = 0; kq < 100; kq++) a += gS[kq] * W1[kq * 1000 + f];
        s1[f] = fmaxf(a, 0.f);
    }
    __syncthreads();

    if (t < 200) {
        int f = t % 100, hh = t / 100;
        float a = 0.f;
        int kq0 = hh * 500;
        for (int kq = kq0; kq < kq0 + 500; kq++) a += s1[kq] * W2[kq * 100 + f];
        part[t] = a;
    }
    __syncthreads();
    if (t < 100) s2[t] = fmaxf(part[t] + part[100 + t] + c2[t], 0.f);
    __syncthreads();

    if (t < 50) {
        float a = c3[t];
        for (int kq = 0; kq < 100; kq++) a += s2[kq] * W3[kq * 50 + t];
        s3[t] = fmaxf(a, 0.f);
    }
    __syncthreads();

    if (t < 32) {
        float a = (t < 50) ? s3[t] * W4[t] : 0.f;
        if (t + 32 < 50) a += s3[t + 32] * W4[t + 32];
        #pragma unroll
        for (int o = 16; o > 0; o >>= 1)
            a += __shfl_xor_sync(0xffffffffu, a, o);
        if (t == 0) out[g] = a + c4[0];
    }
}

// ---------------- launch (7 PDL-chained kernels) ----------------
extern "C" void kernel_launch(void* const* d_in, const int* in_sizes, int n_in,
                              void* d_out, int out_size)
{
    const float* x     = (const float*)d_in[0];
    const int*   eidx  = (const int*)  d_in[1];
    const float* eattr = (const float*)d_in[2];
    const int*   batch = (const int*)  d_in[3];
    const float *We1 = (const float*)d_in[4],  *be1 = (const float*)d_in[5];
    const float *ro1 = (const float*)d_in[6],  *b1  = (const float*)d_in[7];
    const float *We2 = (const float*)d_in[8],  *be2 = (const float*)d_in[9];
    const float *ro2 = (const float*)d_in[10], *b2  = (const float*)d_in[11];
    const float *We3 = (const float*)d_in[12], *be3 = (const float*)d_in[13];
    const float *ro3 = (const float*)d_in[14], *b3  = (const float*)d_in[15];
    const float *W1  = (const float*)d_in[16], *c1  = (const float*)d_in[17];
    const float *W2  = (const float*)d_in[18], *c2  = (const float*)d_in[19];
    const float *W3  = (const float*)d_in[20], *c3  = (const float*)d_in[21];
    const float *W4  = (const float*)d_in[22], *c4  = (const float*)d_in[23];

    float *A1T, *A2T, *A3T, *Z1, *Z2, *Z3;
    cudaGetSymbolAddress((void**)&A1T, g_A1T);
    cudaGetSymbolAddress((void**)&A2T, g_A2T);
    cudaGetSymbolAddress((void**)&A3T, g_A3T);
    cudaGetSymbolAddress((void**)&Z1,  g_Z1);
    cudaGetSymbolAddress((void**)&Z2,  g_Z2);
    cudaGetSymbolAddress((void**)&Z3,  g_Z3);

    cudaLaunchAttribute attr;
    attr.id = cudaLaunchAttributeProgrammaticStreamSerialization;
    attr.val.programmaticStreamSerializationAllowed = 1;

    auto mkcfg = [&](int gx, int gy, int nt) {
        cudaLaunchConfig_t cf{};
        cf.gridDim  = dim3((unsigned)gx, (unsigned)gy, 1);
        cf.blockDim = dim3((unsigned)nt, 1, 1);
        cf.dynamicSmemBytes = 0;
        cf.stream = 0;
        cf.attrs = &attr;
        cf.numAttrs = 1;
        return cf;
    };

    cudaLaunchConfig_t cf;

    // 1) prep: P + layer-1 A'' + zero Z2/Z3
    cf = mkcfg(2, 1, 128);
    cudaLaunchKernelEx(&cf, prep, x, eidx, eattr);

    // 2) main1: Z1 = A1'' @ B1'  (K'=54, 16 col tiles, direct store)
    cf = mkcfg(16, 1, 128);
    cudaLaunchKernelEx(&cf, gemm_main, (const float*)A1T, K1, O1,
                       We1, be1, ro1, Z1, 6 * K1, 1);

    // 3) relu + build layer-2 A''
    cf = mkcfg(125, 1, 128);
    cudaLaunchKernelEx(&cf, relu_buildM, (const float*)Z1, b1, O1, A2T);

    // 4) main2: Z2 += A2'' @ B2'  (K'=12000: 4 col tiles x 125 slices of 96)
    cf = mkcfg(4, 125, 128);
    cudaLaunchKernelEx(&cf, gemm_main, (const float*)A2T, K2, O2,
                       We2, be2, ro2, Z2, 96, 0);

    // 5) relu + build layer-3 A''
    cf = mkcfg(32, 1, 128);
    cudaLaunchKernelEx(&cf, relu_buildM, (const float*)Z2, b2, O2, A3T);

    // 6) main3: Z3 += A3'' @ B3'  (K'=3000: 1 col tile x 94 slices of 32)
    cf = mkcfg(1, 94, 128);
    cudaLaunchKernelEx(&cf, gemm_main, (const float*)A3T, K3, O3,
                       We3, be3, ro3, Z3, 32, 0);

    // 7) head (relu of Z3 inline)
    cf = mkcfg(NGRAPH, 1, 256);
    cudaLaunchKernelEx(&cf, head_fused, (const float*)Z3, batch, b3,
                       W1, c1, W2, c2, W3, c3, W4, c4, (float*)d_out);
}